// round 1
// baseline (speedup 1.0000x reference)
#include <cuda_runtime.h>
#include <cstdint>

#define S_LEN 101
#define BATCH 2048
#define HID 200
#define DIN 120
#define DOUT 12
#define M_TOTAL (S_LEN * BATCH)   // 206848

// Scratch (no allocations allowed -> __device__ globals)
__device__ float    g_cur[(size_t)M_TOTAL * HID];     // ~165 MB: layer-1 currents
__device__ unsigned g_spk2[(size_t)M_TOTAL * 7];      // ~5.8 MB: layer-2 spike bitmasks
__device__ float    g_sum3[BATCH * HID];              // 1.6 MB: sum over t of s3

// ---------- packed f32x2 helpers ----------
__device__ __forceinline__ unsigned long long pack2(float lo, float hi) {
    unsigned long long r;
    asm("mov.b64 %0, {%1,%2};" : "=l"(r) : "f"(lo), "f"(hi));
    return r;
}
__device__ __forceinline__ void unpack2(unsigned long long v, float& lo, float& hi) {
    asm("mov.b64 {%0,%1}, %2;" : "=f"(lo), "=f"(hi) : "l"(v));
}
__device__ __forceinline__ unsigned long long fma2(unsigned long long a,
                                                   unsigned long long b,
                                                   unsigned long long c) {
    unsigned long long d;
    asm("fma.rn.f32x2 %0, %1, %2, %3;" : "=l"(d) : "l"(a), "l"(b), "l"(c));
    return d;
}

// ================= Kernel 1: CUR1 = X @ W1 + b1 =================
// M = S*B = 206848 (row = t*B + b), K = 120, N = 200.
// BM=80, BN=200 exact. 250 active threads: tx in [0,25) covers col pairs
// {2*tx + 50*j + [0,1], j=0..3}; ty in [0,10) covers rows ty*8+i.
#define G1_BM 80
#define G1_TM 8
#define G1_TX 25
#define G1_TY 10
#define G1_THREADS 256
#define G1_SMEM ((G1_BM * DIN + DIN * HID) * 4)   // 134400 B

__global__ __launch_bounds__(G1_THREADS, 1)
void gemm1_kernel(const float* __restrict__ x,
                  const float* __restrict__ W1,
                  const float* __restrict__ b1) {
    extern __shared__ float smem[];
    float* As = smem;                 // [80][120]
    float* Bs = smem + G1_BM * DIN;   // [120][200]
    const int tid = threadIdx.x;

    for (int i = tid; i < DIN * HID; i += G1_THREADS) Bs[i] = W1[i];

    const int  tx  = tid % G1_TX;
    const int  ty  = tid / G1_TX;
    const bool act = (tid < G1_TX * G1_TY);

    unsigned long long bias[4];
    if (act) {
        #pragma unroll
        for (int j = 0; j < 4; j++) {
            int c = 2 * tx + 50 * j;
            bias[j] = pack2(b1[c], b1[c + 1]);
        }
    }

    const int ntiles = (M_TOTAL + G1_BM - 1) / G1_BM;   // 2586
    for (int tile = blockIdx.x; tile < ntiles; tile += gridDim.x) {
        __syncthreads();   // protect As (prev readers) & ensure Bs visible (1st iter)
        const int row0 = tile * G1_BM;
        for (int i = tid; i < G1_BM * DIN; i += G1_THREADS) {
            int r = i / DIN, k = i - r * DIN;
            int row = row0 + r;
            float v = 0.f;
            if (row < M_TOTAL) {
                int t = row >> 11;          // / 2048
                int b = row & 2047;
                int c = k / 40, m = k - c * 40;
                v = x[((b * 3 + c) * 101 + t) * 40 + m];
            }
            As[r * DIN + k] = v;
        }
        __syncthreads();

        if (act) {
            unsigned long long acc[G1_TM][4];
            #pragma unroll
            for (int i = 0; i < G1_TM; i++)
                #pragma unroll
                for (int j = 0; j < 4; j++) acc[i][j] = 0ull;

            const float* ap = As + (ty * G1_TM) * DIN;
            const float* bp = Bs + 2 * tx;

            #pragma unroll 4
            for (int k = 0; k < DIN; k++) {
                unsigned long long bfr[4];
                #pragma unroll
                for (int j = 0; j < 4; j++) {
                    float2 bv = *(const float2*)(bp + k * HID + 50 * j);
                    bfr[j] = pack2(bv.x, bv.y);
                }
                #pragma unroll
                for (int i = 0; i < G1_TM; i++) {
                    float a = ap[i * DIN + k];
                    unsigned long long a2 = pack2(a, a);
                    #pragma unroll
                    for (int j = 0; j < 4; j++) acc[i][j] = fma2(a2, bfr[j], acc[i][j]);
                }
            }

            #pragma unroll
            for (int i = 0; i < G1_TM; i++) {
                int row = row0 + ty * G1_TM + i;
                if (row < M_TOTAL) {
                    float* outp = g_cur + (size_t)row * HID;
                    #pragma unroll
                    for (int j = 0; j < 4; j++) {
                        float lo, hi, bl, bh;
                        unpack2(acc[i][j], lo, hi);
                        unpack2(bias[j], bl, bh);
                        int c = 2 * tx + 50 * j;
                        float2 st; st.x = lo + bl; st.y = hi + bh;
                        *(float2*)(outp + c) = st;
                    }
                }
            }
        }
    }
}

// ================= Kernel 2: LIF1 + sparse GEMM2 + LIF2 -> spk2 bits =========
// 3 groups of 224 threads (7 warps each, warp-aligned). Thread n holds v1[n],
// v2[n] for its batch element. Bit-scan over W2 is warp-uniform (no divergence).
#define L_GROUPS 3
#define GW 224
#define L_THREADS (L_GROUPS * GW)               // 672
#define W_SMEM ((HID * HID + 32) * 4)           // 160128 B (+pad for n>=200 lanes)

__global__ __launch_bounds__(L_THREADS, 1)
void lif2_kernel(const float* __restrict__ W2, const float* __restrict__ b2) {
    extern __shared__ float smem[];
    float* Ws = smem;                                  // [200][200] (+pad)
    __shared__ unsigned sw[2][L_GROUPS][7];
    const int tid = threadIdx.x;
    for (int i = tid; i < HID * HID; i += L_THREADS) Ws[i] = W2[i];

    const int  grp = tid / GW;
    const int  n   = tid - grp * GW;       // 0..223, active n<200
    const bool nv  = (n < HID);
    const float bias = nv ? b2[n] : 0.f;
    __syncthreads();

    for (int b0 = blockIdx.x * L_GROUPS; b0 < BATCH; b0 += gridDim.x * L_GROUPS) {
        const int  b    = b0 + grp;
        const bool bact = (b < BATCH);
        float v1 = 0.f, v2 = 0.f;
        const float*  curp = g_cur  + (size_t)b * HID + (nv ? n : 0);
        unsigned*     spk  = g_spk2 + (size_t)b * 7;

        for (int t = 0; t < S_LEN; t++) {
            float cur = (bact && nv) ? curp[(size_t)t * BATCH * HID] : 0.f;
            v1 = 0.5f * (v1 + cur);
            bool s1 = nv && (v1 >= 1.0f);
            if (s1) v1 = 0.f;
            unsigned bal = __ballot_sync(0xffffffffu, s1);
            if ((n & 31) == 0) sw[t & 1][grp][n >> 5] = bal;
            __syncthreads();

            float acc = bias;
            #pragma unroll
            for (int w = 0; w < 7; w++) {
                unsigned u = sw[t & 1][grp][w];
                while (u) {                                   // warp-uniform
                    int h = (w << 5) + __ffs(u) - 1;
                    u &= u - 1;
                    acc += Ws[h * HID + n];
                }
            }
            v2 = 0.5f * (v2 + acc);
            bool s2 = nv && (v2 >= 1.0f);
            if (s2) v2 = 0.f;
            unsigned bal2 = __ballot_sync(0xffffffffu, s2);
            if (bact && (n & 31) == 0) spk[(size_t)t * BATCH * 7 + (n >> 5)] = bal2;
        }
    }
}

// ================= Kernel 3: sparse GEMM3 + LIF3 -> sum over t of s3 =========
__global__ __launch_bounds__(L_THREADS, 1)
void lif3_kernel(const float* __restrict__ W3, const float* __restrict__ b3) {
    extern __shared__ float smem[];
    float* Ws = smem;
    const int tid = threadIdx.x;
    for (int i = tid; i < HID * HID; i += L_THREADS) Ws[i] = W3[i];

    const int  grp = tid / GW;
    const int  n   = tid - grp * GW;
    const bool nv  = (n < HID);
    const float bias = nv ? b3[n] : 0.f;
    __syncthreads();

    for (int b0 = blockIdx.x * L_GROUPS; b0 < BATCH; b0 += gridDim.x * L_GROUPS) {
        const int b = b0 + grp;
        if (b >= BATCH) continue;          // no barriers below -> safe
        float v3 = 0.f;
        int cnt = 0;
        const unsigned* spk = g_spk2 + (size_t)b * 7;
        for (int t = 0; t < S_LEN; t++) {
            const unsigned* sp = spk + (size_t)t * BATCH * 7;
            float acc = bias;
            #pragma unroll
            for (int w = 0; w < 7; w++) {
                unsigned u = __ldg(sp + w);
                while (u) {                                   // warp-uniform
                    int h = (w << 5) + __ffs(u) - 1;
                    u &= u - 1;
                    acc += Ws[h * HID + n];
                }
            }
            v3 = 0.5f * (v3 + acc);
            if (v3 >= 1.0f) { v3 = 0.f; cnt++; }
        }
        if (nv) g_sum3[b * HID + n] = (float)cnt;
    }
}

// ================= Kernel 4: readout + log_softmax ===========================
// One warp per batch element. logits = (sum3/101) @ Wr + br.
__global__ __launch_bounds__(256)
void readout_kernel(const float* __restrict__ Wr, const float* __restrict__ br,
                    float* __restrict__ out) {
    int warp = (blockIdx.x * blockDim.x + threadIdx.x) >> 5;
    int lane = threadIdx.x & 31;
    if (warp >= BATCH) return;
    const float* srow = g_sum3 + warp * HID;

    float o = -3.0e38f;
    if (lane < DOUT) {
        float acc = br[lane];
        const float inv = 1.0f / 101.0f;
        for (int k = 0; k < HID; k++)
            acc += (srow[k] * inv) * Wr[k * DOUT + lane];
        o = acc;
    }
    float m = o;
    #pragma unroll
    for (int off = 16; off; off >>= 1)
        m = fmaxf(m, __shfl_xor_sync(0xffffffffu, m, off));
    float e = (lane < DOUT) ? expf(o - m) : 0.f;
    float ssum = e;
    #pragma unroll
    for (int off = 16; off; off >>= 1)
        ssum += __shfl_xor_sync(0xffffffffu, ssum, off);
    if (lane < DOUT) out[warp * DOUT + lane] = (o - m) - logf(ssum);
}

// ================= launch ====================================================
extern "C" void kernel_launch(void* const* d_in, const int* in_sizes, int n_in,
                              void* d_out, int out_size) {
    const float* x  = (const float*)d_in[0];
    const float* W1 = (const float*)d_in[1];
    const float* b1 = (const float*)d_in[2];
    const float* W2 = (const float*)d_in[3];
    const float* b2 = (const float*)d_in[4];
    const float* W3 = (const float*)d_in[5];
    const float* b3 = (const float*)d_in[6];
    const float* Wr = (const float*)d_in[7];
    const float* br = (const float*)d_in[8];
    float* out = (float*)d_out;

    cudaFuncSetAttribute(gemm1_kernel, cudaFuncAttributeMaxDynamicSharedMemorySize, G1_SMEM);
    cudaFuncSetAttribute(lif2_kernel,  cudaFuncAttributeMaxDynamicSharedMemorySize, W_SMEM);
    cudaFuncSetAttribute(lif3_kernel,  cudaFuncAttributeMaxDynamicSharedMemorySize, W_SMEM);

    const int grid = 148;   // 1 CTA/SM (smem-bound); persistent stride loops

    gemm1_kernel<<<grid, G1_THREADS, G1_SMEM>>>(x, W1, b1);
    lif2_kernel <<<grid, L_THREADS,  W_SMEM>>>(W2, b2);
    lif3_kernel <<<grid, L_THREADS,  W_SMEM>>>(W3, b3);
    readout_kernel<<<(BATCH * 32) / 256, 256>>>(Wr, br, out);
}

// round 2
// speedup vs baseline: 1.3206x; 1.3206x over previous
#include <cuda_runtime.h>
#include <cstdint>

#define S_LEN 101
#define BATCH 2048
#define HID 200
#define DIN 120
#define DOUT 12
#define M_TOTAL (S_LEN * BATCH)   // 206848

// Scratch (no allocations allowed -> __device__ globals)
// b-major layouts: cur[b][t][n], spk2[b][t][w]
__device__ float    g_cur[(size_t)M_TOTAL * HID];     // ~165 MB
__device__ unsigned g_spk2[(size_t)M_TOTAL * 7];      // ~5.8 MB

// ---------- packed f32x2 helpers ----------
__device__ __forceinline__ unsigned long long pack2(float lo, float hi) {
    unsigned long long r;
    asm("mov.b64 %0, {%1,%2};" : "=l"(r) : "f"(lo), "f"(hi));
    return r;
}
__device__ __forceinline__ void unpack2(unsigned long long v, float& lo, float& hi) {
    asm("mov.b64 {%0,%1}, %2;" : "=f"(lo), "=f"(hi) : "l"(v));
}
__device__ __forceinline__ unsigned long long fma2(unsigned long long a,
                                                   unsigned long long b,
                                                   unsigned long long c) {
    unsigned long long d;
    asm("fma.rn.f32x2 %0, %1, %2, %3;" : "=l"(d) : "l"(a), "l"(b), "l"(c));
    return d;
}

// ================= Kernel 1: CUR1 = X @ W1 + b1 =================
// M = B*S (row = b*101 + t  -> b-major output), K = 120, N = 200.
#define G1_BM 80
#define G1_TM 8
#define G1_TX 25
#define G1_TY 10
#define G1_THREADS 256
#define G1_SMEM ((G1_BM * DIN + DIN * HID) * 4)   // 134400 B

__global__ __launch_bounds__(G1_THREADS, 1)
void gemm1_kernel(const float* __restrict__ x,
                  const float* __restrict__ W1,
                  const float* __restrict__ b1) {
    extern __shared__ float smem[];
    float* As = smem;                 // [80][120]
    float* Bs = smem + G1_BM * DIN;   // [120][200]
    const int tid = threadIdx.x;

    for (int i = tid; i < DIN * HID; i += G1_THREADS) Bs[i] = W1[i];

    const int  tx  = tid % G1_TX;
    const int  ty  = tid / G1_TX;
    const bool act = (tid < G1_TX * G1_TY);

    unsigned long long bias[4];
    if (act) {
        #pragma unroll
        for (int j = 0; j < 4; j++) {
            int c = 2 * tx + 50 * j;
            bias[j] = pack2(b1[c], b1[c + 1]);
        }
    }

    const int ntiles = (M_TOTAL + G1_BM - 1) / G1_BM;   // 2586
    for (int tile = blockIdx.x; tile < ntiles; tile += gridDim.x) {
        __syncthreads();   // protect As (prev readers) & ensure Bs visible (1st iter)
        const int row0 = tile * G1_BM;
        for (int i = tid; i < G1_BM * DIN; i += G1_THREADS) {
            int r = i / DIN, k = i - r * DIN;
            int row = row0 + r;
            float v = 0.f;
            if (row < M_TOTAL) {
                int b = row / S_LEN;
                int t = row - b * S_LEN;
                int c = k / 40, m = k - c * 40;
                v = x[((b * 3 + c) * S_LEN + t) * 40 + m];
            }
            As[r * DIN + k] = v;
        }
        __syncthreads();

        if (act) {
            unsigned long long acc[G1_TM][4];
            #pragma unroll
            for (int i = 0; i < G1_TM; i++)
                #pragma unroll
                for (int j = 0; j < 4; j++) acc[i][j] = 0ull;

            const float* ap = As + (ty * G1_TM) * DIN;
            const float* bp = Bs + 2 * tx;

            #pragma unroll 4
            for (int k = 0; k < DIN; k++) {
                unsigned long long bfr[4];
                #pragma unroll
                for (int j = 0; j < 4; j++) {
                    float2 bv = *(const float2*)(bp + k * HID + 50 * j);
                    bfr[j] = pack2(bv.x, bv.y);
                }
                #pragma unroll
                for (int i = 0; i < G1_TM; i++) {
                    float a = ap[i * DIN + k];
                    unsigned long long a2 = pack2(a, a);
                    #pragma unroll
                    for (int j = 0; j < 4; j++) acc[i][j] = fma2(a2, bfr[j], acc[i][j]);
                }
            }

            #pragma unroll
            for (int i = 0; i < G1_TM; i++) {
                int row = row0 + ty * G1_TM + i;
                if (row < M_TOTAL) {
                    float* outp = g_cur + (size_t)row * HID;   // b-major: row=b*101+t
                    #pragma unroll
                    for (int j = 0; j < 4; j++) {
                        float lo, hi, bl, bh;
                        unpack2(acc[i][j], lo, hi);
                        unpack2(bias[j], bl, bh);
                        int c = 2 * tx + 50 * j;
                        float2 st; st.x = lo + bl; st.y = hi + bh;
                        *(float2*)(outp + c) = st;
                    }
                }
            }
        }
    }
}

// ================= Kernel 2: LIF1 + sparse GEMM2 + LIF2 -> spk2 bits =========
// 3 independent groups of 224 threads (7 warps) per CTA, named barriers per
// group. cur loads software-pipelined depth 4 (loads are recurrence-independent).
#define L_GROUPS 3
#define GW 224
#define L_THREADS (L_GROUPS * GW)               // 672
#define W_SMEM ((HID * HID + 32) * 4)           // 160128 B

__device__ __forceinline__ void group_bar(int grp) {
    asm volatile("bar.sync %0, %1;" :: "r"(grp + 1), "r"(GW) : "memory");
}

__global__ __launch_bounds__(L_THREADS, 1)
void lif2_kernel(const float* __restrict__ W2, const float* __restrict__ b2) {
    extern __shared__ float smem[];
    float* Ws = smem;                                  // [200][200]
    __shared__ unsigned sw[2][L_GROUPS][7];
    const int tid = threadIdx.x;
    for (int i = tid; i < HID * HID; i += L_THREADS) Ws[i] = W2[i];

    const int  grp = tid / GW;
    const int  n   = tid - grp * GW;       // 0..223, active n<200
    const bool nv  = (n < HID);
    const float bias = nv ? b2[n] : 0.f;
    __syncthreads();

    for (int b0 = blockIdx.x * L_GROUPS; b0 < BATCH; b0 += gridDim.x * L_GROUPS) {
        const int  b    = b0 + grp;
        const bool bact = (b < BATCH);
        float v1 = 0.f, v2 = 0.f;
        const int brd = bact ? b : 0;                      // safe read base
        const float*  curp = g_cur  + (size_t)brd * S_LEN * HID + (nv ? n : 0);
        unsigned*     spk  = g_spk2 + (size_t)brd * S_LEN * 7;

        const int P = 4;
        float buf[P];
        #pragma unroll
        for (int i = 0; i < P; i++) buf[i] = curp[(size_t)i * HID];

        for (int t0 = 0; t0 + P <= S_LEN; t0 += P) {       // t = 0..99
            #pragma unroll
            for (int j = 0; j < P; j++) {
                const int t = t0 + j;
                float cur = buf[j];
                int tp = t + P; if (tp > S_LEN - 1) tp = S_LEN - 1;
                buf[j] = curp[(size_t)tp * HID];           // prefetch (indep of v)

                v1 = 0.5f * (v1 + cur);
                bool s1 = nv && (v1 >= 1.0f);
                if (s1) v1 = 0.f;
                unsigned bal = __ballot_sync(0xffffffffu, s1);
                if ((n & 31) == 0) sw[t & 1][grp][n >> 5] = bal;
                group_bar(grp);

                float acc = bias;
                #pragma unroll
                for (int w = 0; w < 7; w++) {
                    unsigned u = sw[t & 1][grp][w];
                    while (u) {                            // warp-uniform
                        int h = (w << 5) + __ffs(u) - 1;
                        u &= u - 1;
                        acc += Ws[h * HID + n];
                    }
                }
                v2 = 0.5f * (v2 + acc);
                bool s2 = nv && (v2 >= 1.0f);
                if (s2) v2 = 0.f;
                unsigned bal2 = __ballot_sync(0xffffffffu, s2);
                if (bact && (n & 31) == 0) spk[(size_t)t * 7 + (n >> 5)] = bal2;
            }
        }
        {   // tail t = 100
            const int t = S_LEN - 1;
            float cur = buf[0];
            v1 = 0.5f * (v1 + cur);
            bool s1 = nv && (v1 >= 1.0f);
            if (s1) v1 = 0.f;
            unsigned bal = __ballot_sync(0xffffffffu, s1);
            if ((n & 31) == 0) sw[t & 1][grp][n >> 5] = bal;
            group_bar(grp);
            float acc = bias;
            #pragma unroll
            for (int w = 0; w < 7; w++) {
                unsigned u = sw[t & 1][grp][w];
                while (u) {
                    int h = (w << 5) + __ffs(u) - 1;
                    u &= u - 1;
                    acc += Ws[h * HID + n];
                }
            }
            v2 = 0.5f * (v2 + acc);
            bool s2 = nv && (v2 >= 1.0f);
            if (s2) v2 = 0.f;
            unsigned bal2 = __ballot_sync(0xffffffffu, s2);
            if (bact && (n & 31) == 0) spk[(size_t)t * 7 + (n >> 5)] = bal2;
        }
    }
}

// ============ Kernel 3: sparse GEMM3 + LIF3 + fused readout/log_softmax ======
__global__ __launch_bounds__(L_THREADS, 1)
void lif3_kernel(const float* __restrict__ W3, const float* __restrict__ b3,
                 const float* __restrict__ Wr, const float* __restrict__ br,
                 float* __restrict__ out) {
    extern __shared__ float smem[];
    float* Ws = smem;
    __shared__ float cnt_sm[L_GROUPS][GW];
    const int tid = threadIdx.x;
    for (int i = tid; i < HID * HID; i += L_THREADS) Ws[i] = W3[i];

    const int  grp  = tid / GW;
    const int  n    = tid - grp * GW;
    const bool nv   = (n < HID);
    const int  lane = n & 31;
    const int  wrp  = n >> 5;              // warp within group, 0..6
    const float bias = nv ? b3[n] : 0.f;
    __syncthreads();

    for (int b0 = blockIdx.x * L_GROUPS; b0 < BATCH; b0 += gridDim.x * L_GROUPS) {
        const int b = b0 + grp;
        if (b >= BATCH) continue;          // group-uniform; no CTA-wide barriers below
        float v3 = 0.f;
        int cnt = 0;
        const unsigned* sp = g_spk2 + (size_t)b * S_LEN * 7;

        unsigned curm[7];
        #pragma unroll
        for (int w = 0; w < 7; w++) curm[w] = __ldg(sp + w);

        for (int t = 0; t < S_LEN; t++) {
            unsigned nxtm[7];
            const unsigned* spn = sp + (size_t)((t + 1 < S_LEN) ? t + 1 : t) * 7;
            #pragma unroll
            for (int w = 0; w < 7; w++) nxtm[w] = __ldg(spn + w);   // prefetch

            float acc = bias;
            #pragma unroll
            for (int w = 0; w < 7; w++) {
                unsigned u = curm[w];
                while (u) {                                   // warp-uniform
                    int h = (w << 5) + __ffs(u) - 1;
                    u &= u - 1;
                    acc += Ws[h * HID + n];
                }
            }
            v3 = 0.5f * (v3 + acc);
            if (v3 >= 1.0f) { v3 = 0.f; cnt++; }
            #pragma unroll
            for (int w = 0; w < 7; w++) curm[w] = nxtm[w];
        }
        cnt_sm[grp][n] = nv ? (float)cnt : 0.f;
        group_bar(grp);

        if (wrp == 0) {                    // warp 0 of group: readout for this b
            float o = -3.0e38f;
            if (lane < DOUT) {
                float acc = 0.f;
                #pragma unroll 4
                for (int k = 0; k < HID; k++)
                    acc += cnt_sm[grp][k] * Wr[k * DOUT + lane];
                o = acc * (1.0f / 101.0f) + br[lane];
            }
            float m = o;
            #pragma unroll
            for (int off = 16; off; off >>= 1)
                m = fmaxf(m, __shfl_xor_sync(0xffffffffu, m, off));
            float e = (lane < DOUT) ? expf(o - m) : 0.f;
            float ssum = e;
            #pragma unroll
            for (int off = 16; off; off >>= 1)
                ssum += __shfl_xor_sync(0xffffffffu, ssum, off);
            if (lane < DOUT) out[b * DOUT + lane] = (o - m) - logf(ssum);
        }
        group_bar(grp);                    // protect cnt_sm before next b iter
    }
}

// ================= launch ====================================================
extern "C" void kernel_launch(void* const* d_in, const int* in_sizes, int n_in,
                              void* d_out, int out_size) {
    const float* x  = (const float*)d_in[0];
    const float* W1 = (const float*)d_in[1];
    const float* b1 = (const float*)d_in[2];
    const float* W2 = (const float*)d_in[3];
    const float* b2 = (const float*)d_in[4];
    const float* W3 = (const float*)d_in[5];
    const float* b3 = (const float*)d_in[6];
    const float* Wr = (const float*)d_in[7];
    const float* br = (const float*)d_in[8];
    float* out = (float*)d_out;

    cudaFuncSetAttribute(gemm1_kernel, cudaFuncAttributeMaxDynamicSharedMemorySize, G1_SMEM);
    cudaFuncSetAttribute(lif2_kernel,  cudaFuncAttributeMaxDynamicSharedMemorySize, W_SMEM);
    cudaFuncSetAttribute(lif3_kernel,  cudaFuncAttributeMaxDynamicSharedMemorySize, W_SMEM);

    const int grid = 148;   // 1 CTA/SM (smem-bound); persistent stride loops

    gemm1_kernel<<<grid, G1_THREADS, G1_SMEM>>>(x, W1, b1);
    lif2_kernel <<<grid, L_THREADS,  W_SMEM>>>(W2, b2);
    lif3_kernel <<<grid, L_THREADS,  W_SMEM>>>(W3, b3, Wr, br, out);
}

// round 3
// speedup vs baseline: 1.6479x; 1.2479x over previous
#include <cuda_runtime.h>
#include <cstdint>

#define S_LEN 101
#define BATCH 2048
#define HID 200
#define DIN 120
#define DOUT 12
#define M_TOTAL (S_LEN * BATCH)   // 206848

// Scratch (no allocations allowed -> __device__ globals)
// b-major layouts: cur[b][t][n], spk2[b][t][w]
__device__ float    g_cur[(size_t)M_TOTAL * HID];     // ~165 MB
__device__ unsigned g_spk2[(size_t)M_TOTAL * 7];      // ~5.8 MB

// ---------- packed f32x2 helpers ----------
__device__ __forceinline__ unsigned long long pack2(float lo, float hi) {
    unsigned long long r;
    asm("mov.b64 %0, {%1,%2};" : "=l"(r) : "f"(lo), "f"(hi));
    return r;
}
__device__ __forceinline__ void unpack2(unsigned long long v, float& lo, float& hi) {
    asm("mov.b64 {%0,%1}, %2;" : "=f"(lo), "=f"(hi) : "l"(v));
}
__device__ __forceinline__ unsigned long long fma2(unsigned long long a,
                                                   unsigned long long b,
                                                   unsigned long long c) {
    unsigned long long d;
    asm("fma.rn.f32x2 %0, %1, %2, %3;" : "=l"(d) : "l"(a), "l"(b), "l"(c));
    return d;
}

// ================= Kernel 1: CUR1 = X @ W1 + b1 =================
// M = B*S (row = b*101 + t -> b-major output), K = 120, N = 200.
// 512 threads (500 active): tx in [0,25) covers col pairs {2tx+50j}, j=0..3;
// ty in [0,20) covers rows ty*6+i. 16 warps/CTA = 4/SMSP.
#define G1_BM 120
#define G1_TM 6
#define G1_TX 25
#define G1_TY 20
#define G1_THREADS 512
#define G1_SMEM ((G1_BM * DIN + DIN * HID) * 4)   // 153600 B

__global__ __launch_bounds__(G1_THREADS, 1)
void gemm1_kernel(const float* __restrict__ x,
                  const float* __restrict__ W1,
                  const float* __restrict__ b1) {
    extern __shared__ float smem[];
    float* As = smem;                 // [120][120]  (row-major, k contiguous)
    float* Bs = smem + G1_BM * DIN;   // [120][200]
    const int tid = threadIdx.x;

    for (int i = tid; i < DIN * HID; i += G1_THREADS) Bs[i] = W1[i];

    const int  tx  = tid % G1_TX;
    const int  ty  = tid / G1_TX;
    const bool act = (tid < G1_TX * G1_TY);

    unsigned long long bias[4];
    if (act) {
        #pragma unroll
        for (int j = 0; j < 4; j++) {
            int c = 2 * tx + 50 * j;
            bias[j] = pack2(b1[c], b1[c + 1]);
        }
    }

    const int ntiles = (M_TOTAL + G1_BM - 1) / G1_BM;   // 1724
    for (int tile = blockIdx.x; tile < ntiles; tile += gridDim.x) {
        __syncthreads();   // protect As (prev readers) & ensure Bs visible (1st iter)
        const int row0 = tile * G1_BM;
        for (int i = tid; i < G1_BM * DIN; i += G1_THREADS) {
            int r = i / DIN, k = i - r * DIN;
            int row = row0 + r;
            float v = 0.f;
            if (row < M_TOTAL) {
                int b = row / S_LEN;
                int t = row - b * S_LEN;
                int c = k / 40, m = k - c * 40;
                v = x[((b * 3 + c) * S_LEN + t) * 40 + m];
            }
            As[r * DIN + k] = v;
        }
        __syncthreads();

        if (act) {
            unsigned long long acc[G1_TM][4];
            #pragma unroll
            for (int i = 0; i < G1_TM; i++)
                #pragma unroll
                for (int j = 0; j < 4; j++) acc[i][j] = 0ull;

            const float* ap = As + (ty * G1_TM) * DIN;
            const float* bp = Bs + 2 * tx;

            for (int k0 = 0; k0 < DIN; k0 += 4) {
                float4 av[G1_TM];
                #pragma unroll
                for (int i = 0; i < G1_TM; i++)
                    av[i] = *(const float4*)(ap + i * DIN + k0);   // LDS.128

                #pragma unroll
                for (int kk = 0; kk < 4; kk++) {
                    unsigned long long bfr[4];
                    #pragma unroll
                    for (int j = 0; j < 4; j++) {
                        float2 bv = *(const float2*)(bp + (k0 + kk) * HID + 50 * j);
                        bfr[j] = pack2(bv.x, bv.y);
                    }
                    #pragma unroll
                    for (int i = 0; i < G1_TM; i++) {
                        float a = (kk == 0) ? av[i].x : (kk == 1) ? av[i].y
                                : (kk == 2) ? av[i].z : av[i].w;
                        unsigned long long a2 = pack2(a, a);
                        #pragma unroll
                        for (int j = 0; j < 4; j++)
                            acc[i][j] = fma2(a2, bfr[j], acc[i][j]);
                    }
                }
            }

            #pragma unroll
            for (int i = 0; i < G1_TM; i++) {
                int row = row0 + ty * G1_TM + i;
                if (row < M_TOTAL) {
                    float* outp = g_cur + (size_t)row * HID;   // b-major: row=b*101+t
                    #pragma unroll
                    for (int j = 0; j < 4; j++) {
                        float lo, hi, bl, bh;
                        unpack2(acc[i][j], lo, hi);
                        unpack2(bias[j], bl, bh);
                        int c = 2 * tx + 50 * j;
                        float2 st; st.x = lo + bl; st.y = hi + bh;
                        *(float2*)(outp + c) = st;
                    }
                }
            }
        }
    }
}

// ================= Kernel 2: LIF1 + sparse GEMM2 + LIF2 -> spk2 bits =========
// 3 independent groups of 224 threads (7 warps) per CTA, named barriers per
// group. cur loads software-pipelined depth 4 (loads are recurrence-independent).
#define L_GROUPS 3
#define GW 224
#define L_THREADS (L_GROUPS * GW)               // 672
#define W_SMEM ((HID * HID + 32) * 4)           // 160128 B

__device__ __forceinline__ void group_bar(int grp) {
    asm volatile("bar.sync %0, %1;" :: "r"(grp + 1), "r"(GW) : "memory");
}

// Warp-uniform sparse row-sum over smem weights; dual accumulators to halve
// the dependent-FADD chain depth.
__device__ __forceinline__ float spike_scan(const unsigned* m, const float* Ws,
                                            int n, float bias) {
    float acc0 = bias, acc1 = 0.f;
    #pragma unroll
    for (int w = 0; w < 7; w += 2) {
        unsigned u = m[w];
        while (u) {
            int h = (w << 5) + __ffs(u) - 1;
            u &= u - 1;
            acc0 += Ws[h * HID + n];
        }
    }
    #pragma unroll
    for (int w = 1; w < 7; w += 2) {
        unsigned u = m[w];
        while (u) {
            int h = (w << 5) + __ffs(u) - 1;
            u &= u - 1;
            acc1 += Ws[h * HID + n];
        }
    }
    return acc0 + acc1;
}

__global__ __launch_bounds__(L_THREADS, 1)
void lif2_kernel(const float* __restrict__ W2, const float* __restrict__ b2) {
    extern __shared__ float smem[];
    float* Ws = smem;                                  // [200][200]
    __shared__ unsigned sw[2][L_GROUPS][8];
    const int tid = threadIdx.x;
    for (int i = tid; i < HID * HID; i += L_THREADS) Ws[i] = W2[i];

    const int  grp = tid / GW;
    const int  n   = tid - grp * GW;       // 0..223, active n<200
    const bool nv  = (n < HID);
    const float bias = nv ? b2[n] : 0.f;
    __syncthreads();

    for (int b0 = blockIdx.x * L_GROUPS; b0 < BATCH; b0 += gridDim.x * L_GROUPS) {
        const int  b    = b0 + grp;
        const bool bact = (b < BATCH);
        float v1 = 0.f, v2 = 0.f;
        const int brd = bact ? b : 0;                      // safe read base
        const float*  curp = g_cur  + (size_t)brd * S_LEN * HID + (nv ? n : 0);
        unsigned*     spk  = g_spk2 + (size_t)brd * S_LEN * 7;

        const int P = 4;
        float buf[P];
        #pragma unroll
        for (int i = 0; i < P; i++) buf[i] = curp[(size_t)i * HID];

        for (int t0 = 0; t0 + P <= S_LEN; t0 += P) {       // t = 0..99
            #pragma unroll
            for (int j = 0; j < P; j++) {
                const int t = t0 + j;
                float cur = buf[j];
                int tp = t + P; if (tp > S_LEN - 1) tp = S_LEN - 1;
                buf[j] = curp[(size_t)tp * HID];           // prefetch (indep of v)

                v1 = 0.5f * (v1 + cur);
                bool s1 = nv && (v1 >= 1.0f);
                if (s1) v1 = 0.f;
                unsigned bal = __ballot_sync(0xffffffffu, s1);
                if ((n & 31) == 0) sw[t & 1][grp][n >> 5] = bal;
                group_bar(grp);

                float acc = spike_scan(sw[t & 1][grp], Ws, n, bias);
                v2 = 0.5f * (v2 + acc);
                bool s2 = nv && (v2 >= 1.0f);
                if (s2) v2 = 0.f;
                unsigned bal2 = __ballot_sync(0xffffffffu, s2);
                if (bact && (n & 31) == 0) spk[(size_t)t * 7 + (n >> 5)] = bal2;
            }
        }
        {   // tail t = 100
            const int t = S_LEN - 1;
            float cur = buf[0];
            v1 = 0.5f * (v1 + cur);
            bool s1 = nv && (v1 >= 1.0f);
            if (s1) v1 = 0.f;
            unsigned bal = __ballot_sync(0xffffffffu, s1);
            if ((n & 31) == 0) sw[t & 1][grp][n >> 5] = bal;
            group_bar(grp);
            float acc = spike_scan(sw[t & 1][grp], Ws, n, bias);
            v2 = 0.5f * (v2 + acc);
            bool s2 = nv && (v2 >= 1.0f);
            if (s2) v2 = 0.f;
            unsigned bal2 = __ballot_sync(0xffffffffu, s2);
            if (bact && (n & 31) == 0) spk[(size_t)t * 7 + (n >> 5)] = bal2;
        }
    }
}

// ============ Kernel 3: sparse GEMM3 + LIF3 + fused readout/log_softmax ======
__global__ __launch_bounds__(L_THREADS, 1)
void lif3_kernel(const float* __restrict__ W3, const float* __restrict__ b3,
                 const float* __restrict__ Wr, const float* __restrict__ br,
                 float* __restrict__ out) {
    extern __shared__ float smem[];
    float* Ws = smem;
    __shared__ float cnt_sm[L_GROUPS][GW];
    const int tid = threadIdx.x;
    for (int i = tid; i < HID * HID; i += L_THREADS) Ws[i] = W3[i];

    const int  grp  = tid / GW;
    const int  n    = tid - grp * GW;
    const bool nv   = (n < HID);
    const int  lane = n & 31;
    const int  wrp  = n >> 5;              // warp within group, 0..6
    const float bias = nv ? b3[n] : 0.f;
    __syncthreads();

    for (int b0 = blockIdx.x * L_GROUPS; b0 < BATCH; b0 += gridDim.x * L_GROUPS) {
        const int b = b0 + grp;
        if (b >= BATCH) continue;          // group-uniform; no CTA-wide barriers below
        float v3 = 0.f;
        int cnt = 0;
        const unsigned* sp = g_spk2 + (size_t)b * S_LEN * 7;

        unsigned curm[7];
        #pragma unroll
        for (int w = 0; w < 7; w++) curm[w] = __ldg(sp + w);

        for (int t = 0; t < S_LEN; t++) {
            unsigned nxtm[7];
            const unsigned* spn = sp + (size_t)((t + 1 < S_LEN) ? t + 1 : t) * 7;
            #pragma unroll
            for (int w = 0; w < 7; w++) nxtm[w] = __ldg(spn + w);   // prefetch

            float acc = spike_scan(curm, Ws, n, bias);
            v3 = 0.5f * (v3 + acc);
            if (v3 >= 1.0f) { v3 = 0.f; cnt++; }
            #pragma unroll
            for (int w = 0; w < 7; w++) curm[w] = nxtm[w];
        }
        cnt_sm[grp][n] = nv ? (float)cnt : 0.f;
        group_bar(grp);

        if (wrp == 0) {                    // warp 0 of group: readout for this b
            float o = -3.0e38f;
            if (lane < DOUT) {
                float acc = 0.f;
                #pragma unroll 4
                for (int k = 0; k < HID; k++)
                    acc += cnt_sm[grp][k] * Wr[k * DOUT + lane];
                o = acc * (1.0f / 101.0f) + br[lane];
            }
            float m = o;
            #pragma unroll
            for (int off = 16; off; off >>= 1)
                m = fmaxf(m, __shfl_xor_sync(0xffffffffu, m, off));
            float e = (lane < DOUT) ? expf(o - m) : 0.f;
            float ssum = e;
            #pragma unroll
            for (int off = 16; off; off >>= 1)
                ssum += __shfl_xor_sync(0xffffffffu, ssum, off);
            if (lane < DOUT) out[b * DOUT + lane] = (o - m) - logf(ssum);
        }
        group_bar(grp);                    // protect cnt_sm before next b iter
    }
}

// ================= launch ====================================================
extern "C" void kernel_launch(void* const* d_in, const int* in_sizes, int n_in,
                              void* d_out, int out_size) {
    const float* x  = (const float*)d_in[0];
    const float* W1 = (const float*)d_in[1];
    const float* b1 = (const float*)d_in[2];
    const float* W2 = (const float*)d_in[3];
    const float* b2 = (const float*)d_in[4];
    const float* W3 = (const float*)d_in[5];
    const float* b3 = (const float*)d_in[6];
    const float* Wr = (const float*)d_in[7];
    const float* br = (const float*)d_in[8];
    float* out = (float*)d_out;

    cudaFuncSetAttribute(gemm1_kernel, cudaFuncAttributeMaxDynamicSharedMemorySize, G1_SMEM);
    cudaFuncSetAttribute(lif2_kernel,  cudaFuncAttributeMaxDynamicSharedMemorySize, W_SMEM);
    cudaFuncSetAttribute(lif3_kernel,  cudaFuncAttributeMaxDynamicSharedMemorySize, W_SMEM);

    const int grid = 148;   // 1 CTA/SM (smem-bound); persistent stride loops

    gemm1_kernel<<<grid, G1_THREADS, G1_SMEM>>>(x, W1, b1);
    lif2_kernel <<<grid, L_THREADS,  W_SMEM>>>(W2, b2);
    lif3_kernel <<<grid, L_THREADS,  W_SMEM>>>(W3, b3, Wr, br, out);
}